// round 4
// baseline (speedup 1.0000x reference)
#include <cuda_runtime.h>

// ---------------------------------------------------------------------------
// Problem constants
// ---------------------------------------------------------------------------
namespace {
constexpr int   N    = 4096;
constexpr int   DIM  = 100;
constexpr int   HID  = 110;
constexpr int   T    = 50;
constexpr float DT   = 0.02f;     // float32(1.0/50.0)
constexpr float EPS  = 1e-6f;
}

// ---------------------------------------------------------------------------
// Persistent device state (static globals — no allocations allowed)
// ---------------------------------------------------------------------------
__device__ float g_dwT[(size_t)T * N * DIM];   // dw transposed to [T][N][DIM]
__device__ float g_x [N * DIM];
__device__ float g_y [N];
__device__ float g_h1[N * HID];
__device__ float g_h2[N * HID];
__device__ float g_h3[N * DIM];
__device__ float g_s0[2 * DIM];   // [sum(DIM), sumsq(DIM)] for BN0 input (x)
__device__ float g_s1[2 * HID];   // stats of GEMM1 output
__device__ float g_s2[2 * HID];   // stats of GEMM2 output
__device__ float g_s3[2 * DIM];   // stats of GEMM3 output (+bias)
__device__ float g_acc[2];        // [sum smoothl1, sum ye]

// BN affine from accumulated stats: returns a, c with bn(x) = a*x + c
__device__ __forceinline__ void affine_coef(float sum, float sumsq, float w,
                                            float b, float& a, float& c) {
    float mean = sum * (1.0f / N);
    float var  = fmaf(-mean, mean, sumsq * (1.0f / N)) + EPS;
    float r    = rsqrtf(var);
    r = r * (1.5f - 0.5f * var * r * r);   // Newton refine
    a = w * r;
    c = fmaf(-mean, a, b);
}

// ---------------------------------------------------------------------------
// Init: zero stat buffers + loss accumulators (must happen every replay)
// ---------------------------------------------------------------------------
__global__ void initK() {
    int tid = threadIdx.x;
    for (int k = tid; k < 2 * DIM; k += 256) { g_s0[k] = 0.f; g_s3[k] = 0.f; }
    for (int k = tid; k < 2 * HID; k += 256) { g_s1[k] = 0.f; g_s2[k] = 0.f; }
    if (tid < 2) g_acc[tid] = 0.f;
}

// ---------------------------------------------------------------------------
// Transpose dw [N*DIM, T] -> [T, N*DIM] (coalesced both sides via smem tile)
// grid (N*DIM/32, 2), block (32, 8)
// ---------------------------------------------------------------------------
__global__ void transpose_dw(const float* __restrict__ in) {
    __shared__ float s[32][33];
    const int ij0 = blockIdx.x * 32;
    const int t0  = blockIdx.y * 32;
    const int tx  = threadIdx.x, ty = threadIdx.y;
#pragma unroll
    for (int i = 0; i < 32; i += 8) {
        int t = t0 + tx;
        int ij = ij0 + ty + i;
        if (t < T) s[ty + i][tx] = in[(size_t)ij * T + t];
    }
    __syncthreads();
#pragma unroll
    for (int i = 0; i < 32; i += 8) {
        int t = t0 + ty + i;
        int ij = ij0 + tx;
        if (t < T) g_dwT[(size_t)t * (N * DIM) + ij] = s[tx][ty + i];
    }
}

// ---------------------------------------------------------------------------
// Phase A, step 0: z = z_init (broadcast), x = 0, y = y_init
// grid 128, block 256 (warp per row, 4 row-iterations)
// ---------------------------------------------------------------------------
__global__ void __launch_bounds__(256) phaseA0(const float* __restrict__ zinit,
                                               const float* __restrict__ yinit,
                                               float* __restrict__ out_xs,
                                               float* __restrict__ out_us) {
    __shared__ float ssum[DIM], ssq[DIM];
    const int tid = threadIdx.x;
    for (int k = tid; k < DIM; k += 256) { ssum[k] = 0.f; ssq[k] = 0.f; }
    __syncthreads();
    const int warp = tid >> 5, lane = tid & 31;
    const float y0 = yinit[0];
    for (int it = 0; it < 4; ++it) {
        const int i = blockIdx.x * 32 + it * 8 + warp;
        float sz = 0.f, zdw = 0.f;
        float zv[4], dwv[4];
#pragma unroll
        for (int c2 = 0; c2 < 4; ++c2) {
            int j = lane + 32 * c2;
            zv[c2] = 0.f; dwv[c2] = 0.f;
            if (j < DIM) {
                zv[c2]  = zinit[j];
                dwv[c2] = g_dwT[(size_t)i * DIM + j];     // t = 0
                sz  += zv[c2];
                zdw += zv[c2] * dwv[c2];
            }
        }
#pragma unroll
        for (int o = 16; o; o >>= 1) {
            sz  += __shfl_xor_sync(~0u, sz, o);
            zdw += __shfl_xor_sync(~0u, zdw, o);
        }
        const float u = fminf(fmaxf(-sz, -1.f), 1.f);
        if (lane == 0) {
            float y = y0 - DT * 0.5f * (u * u) + DT * sz * u + zdw;
            g_y[i] = y;
            out_us[i] = u;
        }
#pragma unroll
        for (int c2 = 0; c2 < 4; ++c2) {
            int j = lane + 32 * c2;
            if (j < DIM) {
                out_xs[(size_t)i * DIM + j] = 0.f;        // x_0 = 0
                float xn = fmaf(u, DT, dwv[c2]);          // 0*(1-dt)+u*dt+dw
                g_x[(size_t)i * DIM + j] = xn;
                atomicAdd(&ssum[j], xn);
                atomicAdd(&ssq[j], xn * xn);
            }
        }
    }
    __syncthreads();
    for (int k = tid; k < DIM; k += 256) {
        atomicAdd(&g_s0[k], ssum[k]);
        atomicAdd(&g_s0[DIM + k], ssq[k]);
    }
}

// ---------------------------------------------------------------------------
// Phase A, steps t = 1..48: z from h3 + BN3 stats; u, y, x updates; xs/us;
// accumulate BN0 stats of x_new; zero s1/s2 for this step.
// ---------------------------------------------------------------------------
__global__ void __launch_bounds__(256) phaseA(int t,
                                              const float* __restrict__ bn3w,
                                              const float* __restrict__ bn3b,
                                              float* __restrict__ out_xs,
                                              float* __restrict__ out_us) {
    __shared__ float sAz[DIM], sBz[DIM], ssum[DIM], ssq[DIM];
    const int tid = threadIdx.x;
    for (int k = tid; k < DIM; k += 256) {
        float a, c;
        affine_coef(g_s3[k], g_s3[DIM + k], bn3w[k], bn3b[k], a, c);
        sAz[k] = a * 1e-4f;          // /DIM (subnet) /DIM (z update)
        sBz[k] = c * 1e-4f;
        ssum[k] = 0.f; ssq[k] = 0.f;
    }
    if (blockIdx.x == 0) {
        for (int k = tid; k < 2 * HID; k += 256) { g_s1[k] = 0.f; g_s2[k] = 0.f; }
    }
    __syncthreads();
    const int warp = tid >> 5, lane = tid & 31;
    const float* dwt = g_dwT + (size_t)t * N * DIM;
    float* xsO = out_xs + (size_t)t * N * DIM;
    for (int it = 0; it < 4; ++it) {
        const int i = blockIdx.x * 32 + it * 8 + warp;
        float sz = 0.f, zdw = 0.f, xx = 0.f;
        float zv[4], dwv[4], xv[4];
#pragma unroll
        for (int c2 = 0; c2 < 4; ++c2) {
            int j = lane + 32 * c2;
            if (j < DIM) {
                float h = g_h3[(size_t)i * DIM + j];
                zv[c2]  = fmaf(h, sAz[j], sBz[j]);
                dwv[c2] = dwt[(size_t)i * DIM + j];
                xv[c2]  = g_x[(size_t)i * DIM + j];
                sz  += zv[c2];
                zdw += zv[c2] * dwv[c2];
                xx  += xv[c2] * xv[c2];
            }
        }
#pragma unroll
        for (int o = 16; o; o >>= 1) {
            sz  += __shfl_xor_sync(~0u, sz, o);
            zdw += __shfl_xor_sync(~0u, zdw, o);
            xx  += __shfl_xor_sync(~0u, xx, o);
        }
        const float u = fminf(fmaxf(-sz, -1.f), 1.f);
        if (lane == 0) {
            float y = g_y[i];
            y = y - DT * 0.5f * (xx + u * u) + DT * sz * u + zdw;
            g_y[i] = y;
            out_us[(size_t)t * N + i] = u;
        }
#pragma unroll
        for (int c2 = 0; c2 < 4; ++c2) {
            int j = lane + 32 * c2;
            if (j < DIM) {
                float xo = xv[c2];
                xsO[(size_t)i * DIM + j] = xo;
                float xn = fmaf(xo, 1.0f - DT, fmaf(u, DT, dwv[c2]));
                g_x[(size_t)i * DIM + j] = xn;
                atomicAdd(&ssum[j], xn);
                atomicAdd(&ssq[j], xn * xn);
            }
        }
    }
    __syncthreads();
    for (int k = tid; k < DIM; k += 256) {
        atomicAdd(&g_s0[k], ssum[k]);
        atomicAdd(&g_s0[DIM + k], ssq[k]);
    }
}

// ---------------------------------------------------------------------------
// Fused GEMM + BN:  out[N,C] = bnaffine(in)[N,K] (opt relu) @ W[C,K]^T (+bias)
// Epilogue accumulates next-layer BN stats. 32 rows x 128(pad) cols per block.
// 256 threads = 16 rowgroups (2 rows) x 16 colgroups (8 cols).
// ---------------------------------------------------------------------------
template <int LAYER>
__global__ void __launch_bounds__(256) gemm_bn(const float* __restrict__ W,
                                               const float* __restrict__ bnw,
                                               const float* __restrict__ bnb,
                                               const float* __restrict__ bias) {
    constexpr int  K    = (LAYER == 1) ? DIM : HID;
    constexpr int  C    = (LAYER == 3) ? DIM : HID;
    constexpr bool RELU = (LAYER != 1);
    constexpr bool BIAS = (LAYER == 3);
    constexpr int  CP   = 132;   // padded col stride (16B-aligned, conflict-safe)

    const float* in   = (LAYER == 1) ? (const float*)g_x
                      : (LAYER == 2) ? (const float*)g_h1 : (const float*)g_h2;
    const float* stIn = (LAYER == 1) ? (const float*)g_s0
                      : (LAYER == 2) ? (const float*)g_s1 : (const float*)g_s2;
    float* out  = (LAYER == 1) ? g_h1 : (LAYER == 2) ? g_h2 : g_h3;
    float* stOut = (LAYER == 1) ? g_s1 : (LAYER == 2) ? g_s2 : g_s3;

    extern __shared__ float sm[];
    float* sW = sm;                 // K*CP
    float* sX = sW + K * CP;        // K*34  (transposed input tile)
    float* sA = sX + K * 34;        // K
    float* sB = sA + K;             // K

    const int tid  = threadIdx.x;
    const int rowg = tid & 15, colg = tid >> 4;
    const int row0 = blockIdx.x * 32;

    // rotate-zero the stats buffer that is safe to clear in this phase
    if (blockIdx.x == 0) {
        if (LAYER == 1) for (int k = tid; k < 2 * DIM; k += 256) g_s3[k] = 0.f;
        if (LAYER == 2) for (int k = tid; k < 2 * DIM; k += 256) g_s0[k] = 0.f;
    }

    // BN affine of the input layer
    for (int k = tid; k < K; k += 256) {
        float a, c;
        affine_coef(stIn[k], stIn[K + k], bnw[k], bnb[k], a, c);
        sA[k] = a; sB[k] = c;
    }
    // zero pad columns of sW so pad accumulators stay 0
    for (int idx = tid; idx < K * (CP - C); idx += 256) {
        int k = idx / (CP - C), c = idx - k * (CP - C);
        sW[k * CP + C + c] = 0.f;
    }
    __syncthreads();

    // W is [C,K] row-major -> sW[k][c]
    for (int idx = tid; idx < C * K; idx += 256) {
        int c = idx / K, k = idx - c * K;
        sW[k * CP + c] = W[idx];
    }
    // input tile (affine + optional relu), transposed to sX[k][r]
    for (int idx = tid; idx < 32 * K; idx += 256) {
        int r = idx / K, k = idx - r * K;
        float v = in[(size_t)(row0 + r) * K + k];
        v = fmaf(v, sA[k], sB[k]);
        if (RELU) v = fmaxf(v, 0.f);
        sX[k * 34 + r] = v;
    }
    __syncthreads();

    float acc0[8], acc1[8];
#pragma unroll
    for (int c = 0; c < 8; ++c) { acc0[c] = 0.f; acc1[c] = 0.f; }
    const int cb = colg * 8;

#pragma unroll 2
    for (int k = 0; k < K; ++k) {
        float2 xv = *reinterpret_cast<const float2*>(&sX[k * 34 + 2 * rowg]);
        float4 w0 = *reinterpret_cast<const float4*>(&sW[k * CP + cb]);
        float4 w1 = *reinterpret_cast<const float4*>(&sW[k * CP + cb + 4]);
        float wv[8] = {w0.x, w0.y, w0.z, w0.w, w1.x, w1.y, w1.z, w1.w};
#pragma unroll
        for (int c = 0; c < 8; ++c) {
            acc0[c] = fmaf(xv.x, wv[c], acc0[c]);
            acc1[c] = fmaf(xv.y, wv[c], acc1[c]);
        }
    }

    // epilogue: bias, store, per-column stats (shfl-reduce over 16 rowgroups)
    const int r0 = row0 + 2 * rowg;
    float vs[8], vq[8];
#pragma unroll
    for (int c = 0; c < 8; ++c) {
        const int col = cb + c;
        float v0 = acc0[c], v1 = acc1[c];
        if (BIAS && col < C) { float b = __ldg(&bias[col]); v0 += b; v1 += b; }
        if (col < C) {
            out[(size_t)r0 * C + col]       = v0;
            out[(size_t)(r0 + 1) * C + col] = v1;
        }
        vs[c] = v0 + v1;
        vq[c] = v0 * v0 + v1 * v1;
    }
#pragma unroll
    for (int c = 0; c < 8; ++c) {
        float s = vs[c], q = vq[c];
#pragma unroll
        for (int o = 8; o; o >>= 1) {
            s += __shfl_xor_sync(~0u, s, o);
            q += __shfl_xor_sync(~0u, q, o);
        }
        if ((tid & 15) == 0) {
            const int col = cb + c;
            if (col < C) {
                atomicAdd(&stOut[col], s);
                atomicAdd(&stOut[C + col], q);
            }
        }
    }
}

// ---------------------------------------------------------------------------
// Final step (t = 49): u/y update only, ye, loss partials, outputs
// ---------------------------------------------------------------------------
__global__ void __launch_bounds__(256) finalK(const float* __restrict__ bn3w,
                                              const float* __restrict__ bn3b,
                                              float* __restrict__ out_y,
                                              float* __restrict__ out_ye,
                                              float* __restrict__ out_xs,
                                              float* __restrict__ out_us) {
    __shared__ float sAz[DIM], sBz[DIM];
    const int tid = threadIdx.x;
    for (int k = tid; k < DIM; k += 256) {
        float a, c;
        affine_coef(g_s3[k], g_s3[DIM + k], bn3w[k], bn3b[k], a, c);
        sAz[k] = a * 1e-4f;
        sBz[k] = c * 1e-4f;
    }
    __syncthreads();
    const int warp = tid >> 5, lane = tid & 31;
    const float* dwt = g_dwT + (size_t)(T - 1) * N * DIM;
    float* xsO = out_xs + (size_t)(T - 1) * N * DIM;
    for (int it = 0; it < 4; ++it) {
        const int i = blockIdx.x * 32 + it * 8 + warp;
        float sz = 0.f, zdw = 0.f, xx = 0.f;
#pragma unroll
        for (int c2 = 0; c2 < 4; ++c2) {
            int j = lane + 32 * c2;
            if (j < DIM) {
                float h  = g_h3[(size_t)i * DIM + j];
                float z  = fmaf(h, sAz[j], sBz[j]);
                float dw = dwt[(size_t)i * DIM + j];
                float x  = g_x[(size_t)i * DIM + j];
                xsO[(size_t)i * DIM + j] = x;
                sz += z; zdw += z * dw; xx += x * x;
            }
        }
#pragma unroll
        for (int o = 16; o; o >>= 1) {
            sz  += __shfl_xor_sync(~0u, sz, o);
            zdw += __shfl_xor_sync(~0u, zdw, o);
            xx  += __shfl_xor_sync(~0u, xx, o);
        }
        const float u = fminf(fmaxf(-sz, -1.f), 1.f);
        if (lane == 0) {
            float y = g_y[i];
            y = y - DT * 0.5f * (xx + u * u) + DT * sz * u + zdw;
            out_y[i]  = y;
            float ye  = 0.5f * xx;
            out_ye[i] = ye;
            out_us[(size_t)(T - 1) * N + i] = u;
            float d = y - ye, ad = fabsf(d);
            float sl1 = (ad < 1.f) ? 0.5f * d * d : ad - 0.5f;
            atomicAdd(&g_acc[0], sl1);
            atomicAdd(&g_acc[1], ye);
        }
    }
}

__global__ void lossK(float* __restrict__ out) {
    float m1 = g_acc[0] * (1.0f / N);
    float m2 = g_acc[1] * (1.0f / N);
    out[0] = 100.0f * (m1 + m2 * m2);   // 2 * DELTA_CLIP * (sl1 + mean(ye)^2)
}

// ---------------------------------------------------------------------------
// Launcher (graph-capturable: kernel launches only)
// ---------------------------------------------------------------------------
extern "C" void kernel_launch(void* const* d_in, const int* in_sizes, int n_in,
                              void* d_out, int out_size) {
    const float* dw    = (const float*)d_in[0];
    const float* yinit = (const float*)d_in[1];
    const float* zinit = (const float*)d_in[2];
    const float* bn0w  = (const float*)d_in[3];
    const float* bn0b  = (const float*)d_in[4];
    const float* w1    = (const float*)d_in[5];
    const float* bn1w  = (const float*)d_in[6];
    const float* bn1b  = (const float*)d_in[7];
    const float* w2    = (const float*)d_in[8];
    const float* bn2w  = (const float*)d_in[9];
    const float* bn2b  = (const float*)d_in[10];
    const float* w3    = (const float*)d_in[11];
    const float* b3    = (const float*)d_in[12];
    const float* bn3w  = (const float*)d_in[13];
    const float* bn3b  = (const float*)d_in[14];

    float* out    = (float*)d_out;
    float* out_y  = out + 1;
    float* out_ye = out + 1 + N;
    float* out_xs = out + 1 + 2 * N;
    float* out_us = out_xs + (size_t)T * N * DIM;

    const size_t sm1 = (size_t)(DIM * 132 + DIM * 34 + 2 * DIM) * sizeof(float);
    const size_t sm2 = (size_t)(HID * 132 + HID * 34 + 2 * HID) * sizeof(float);
    cudaFuncSetAttribute(gemm_bn<1>, cudaFuncAttributeMaxDynamicSharedMemorySize, (int)sm1);
    cudaFuncSetAttribute(gemm_bn<2>, cudaFuncAttributeMaxDynamicSharedMemorySize, (int)sm2);
    cudaFuncSetAttribute(gemm_bn<3>, cudaFuncAttributeMaxDynamicSharedMemorySize, (int)sm2);

    initK<<<1, 256>>>();
    transpose_dw<<<dim3(N * DIM / 32, 2), dim3(32, 8)>>>(dw);

    // step 0
    phaseA0<<<128, 256>>>(zinit, yinit, out_xs, out_us);
    gemm_bn<1><<<128, 256, sm1>>>(w1, bn0w, bn0b, nullptr);
    gemm_bn<2><<<128, 256, sm2>>>(w2, bn1w, bn1b, nullptr);
    gemm_bn<3><<<128, 256, sm2>>>(w3, bn2w, bn2b, b3);

    // steps 1..48
    for (int t = 1; t < T - 1; ++t) {
        phaseA<<<128, 256>>>(t, bn3w, bn3b, out_xs, out_us);
        gemm_bn<1><<<128, 256, sm1>>>(w1, bn0w, bn0b, nullptr);
        gemm_bn<2><<<128, 256, sm2>>>(w2, bn1w, bn1b, nullptr);
        gemm_bn<3><<<128, 256, sm2>>>(w3, bn2w, bn2b, b3);
    }

    // final step t = 49 (u/y only) + loss
    finalK<<<128, 256>>>(bn3w, bn3b, out_y, out_ye, out_xs, out_us);
    lossK<<<1, 1>>>(out);
}

// round 5
// speedup vs baseline: 1.0030x; 1.0030x over previous
#include <cuda_runtime.h>

// ---------------------------------------------------------------------------
// Problem constants
// ---------------------------------------------------------------------------
namespace {
constexpr int   N    = 4096;
constexpr int   DIM  = 100;
constexpr int   HID  = 110;
constexpr int   T    = 50;
constexpr float DT   = 0.02f;     // float32(1.0/50.0)
constexpr float EPS  = 1e-6f;
}

// ---------------------------------------------------------------------------
// Persistent device state (static globals — no allocations allowed)
// ---------------------------------------------------------------------------
__device__ float g_dwT[(size_t)T * N * DIM];   // dw transposed to [T][N][DIM]
__device__ float g_x [N * DIM];
__device__ float g_y [N];
__device__ float g_h1[N * HID];
__device__ float g_h2[N * HID];
__device__ float g_h3[N * DIM];
__device__ float g_s0[2 * DIM];   // [sum(DIM), sumsq(DIM)] for BN0 input (x)
__device__ float g_s1[2 * HID];   // stats of GEMM1 output
__device__ float g_s2[2 * HID];   // stats of GEMM2 output
__device__ float g_s3[2 * DIM];   // stats of GEMM3 output (+bias)
__device__ float g_acc[2];        // [sum smoothl1, sum ye]

// BN affine from accumulated stats: returns a, c with bn(x) = a*x + c
__device__ __forceinline__ void affine_coef(float sum, float sumsq, float w,
                                            float b, float& a, float& c) {
    float mean = sum * (1.0f / N);
    float var  = fmaf(-mean, mean, sumsq * (1.0f / N)) + EPS;
    float r    = rsqrtf(var);
    r = r * (1.5f - 0.5f * var * r * r);   // Newton refine
    a = w * r;
    c = fmaf(-mean, a, b);
}

// ---------------------------------------------------------------------------
// Init: zero stat buffers + loss accumulators (must happen every replay)
// ---------------------------------------------------------------------------
__global__ void initK() {
    int tid = threadIdx.x;
    for (int k = tid; k < 2 * DIM; k += 256) { g_s0[k] = 0.f; g_s3[k] = 0.f; }
    for (int k = tid; k < 2 * HID; k += 256) { g_s1[k] = 0.f; g_s2[k] = 0.f; }
    if (tid < 2) g_acc[tid] = 0.f;
}

// ---------------------------------------------------------------------------
// Transpose dw [N*DIM, T] -> [T, N*DIM] (coalesced both sides via smem tile)
// grid (N*DIM/32, 2), block (32, 8)
// ---------------------------------------------------------------------------
__global__ void transpose_dw(const float* __restrict__ in) {
    __shared__ float s[32][33];
    const int ij0 = blockIdx.x * 32;
    const int t0  = blockIdx.y * 32;
    const int tx  = threadIdx.x, ty = threadIdx.y;
#pragma unroll
    for (int i = 0; i < 32; i += 8) {
        int t = t0 + tx;
        int ij = ij0 + ty + i;
        if (t < T) s[ty + i][tx] = in[(size_t)ij * T + t];
    }
    __syncthreads();
#pragma unroll
    for (int i = 0; i < 32; i += 8) {
        int t = t0 + ty + i;
        int ij = ij0 + tx;
        if (t < T) g_dwT[(size_t)t * (N * DIM) + ij] = s[tx][ty + i];
    }
}

// ---------------------------------------------------------------------------
// Phase A, step 0: z = z_init (broadcast), x = 0, y = y_init
// grid 128, block 256 (warp per row, 4 row-iterations)
// ---------------------------------------------------------------------------
__global__ void __launch_bounds__(256) phaseA0(const float* __restrict__ zinit,
                                               const float* __restrict__ yinit,
                                               float* __restrict__ out_xs,
                                               float* __restrict__ out_us) {
    __shared__ float ssum[DIM], ssq[DIM];
    const int tid = threadIdx.x;
    for (int k = tid; k < DIM; k += 256) { ssum[k] = 0.f; ssq[k] = 0.f; }
    __syncthreads();
    const int warp = tid >> 5, lane = tid & 31;
    const float y0 = yinit[0];
    for (int it = 0; it < 4; ++it) {
        const int i = blockIdx.x * 32 + it * 8 + warp;
        float sz = 0.f, zdw = 0.f;
        float zv[4], dwv[4];
#pragma unroll
        for (int c2 = 0; c2 < 4; ++c2) {
            int j = lane + 32 * c2;
            zv[c2] = 0.f; dwv[c2] = 0.f;
            if (j < DIM) {
                zv[c2]  = zinit[j];
                dwv[c2] = g_dwT[(size_t)i * DIM + j];     // t = 0
                sz  += zv[c2];
                zdw += zv[c2] * dwv[c2];
            }
        }
#pragma unroll
        for (int o = 16; o; o >>= 1) {
            sz  += __shfl_xor_sync(~0u, sz, o);
            zdw += __shfl_xor_sync(~0u, zdw, o);
        }
        const float u = fminf(fmaxf(-sz, -1.f), 1.f);
        if (lane == 0) {
            float y = y0 - DT * 0.5f * (u * u) + DT * sz * u + zdw;
            g_y[i] = y;
            out_us[i] = u;
        }
#pragma unroll
        for (int c2 = 0; c2 < 4; ++c2) {
            int j = lane + 32 * c2;
            if (j < DIM) {
                out_xs[(size_t)i * DIM + j] = 0.f;        // x_0 = 0
                float xn = fmaf(u, DT, dwv[c2]);          // 0*(1-dt)+u*dt+dw
                g_x[(size_t)i * DIM + j] = xn;
                atomicAdd(&ssum[j], xn);
                atomicAdd(&ssq[j], xn * xn);
            }
        }
    }
    __syncthreads();
    for (int k = tid; k < DIM; k += 256) {
        atomicAdd(&g_s0[k], ssum[k]);
        atomicAdd(&g_s0[DIM + k], ssq[k]);
    }
}

// ---------------------------------------------------------------------------
// Phase A, steps t = 1..48: z from h3 + BN3 stats; u, y, x updates; xs/us;
// accumulate BN0 stats of x_new; zero s1/s2 for this step.
// ---------------------------------------------------------------------------
__global__ void __launch_bounds__(256) phaseA(int t,
                                              const float* __restrict__ bn3w,
                                              const float* __restrict__ bn3b,
                                              float* __restrict__ out_xs,
                                              float* __restrict__ out_us) {
    __shared__ float sAz[DIM], sBz[DIM], ssum[DIM], ssq[DIM];
    const int tid = threadIdx.x;
    for (int k = tid; k < DIM; k += 256) {
        float a, c;
        affine_coef(g_s3[k], g_s3[DIM + k], bn3w[k], bn3b[k], a, c);
        sAz[k] = a * 1e-4f;          // /DIM (subnet) /DIM (z update)
        sBz[k] = c * 1e-4f;
        ssum[k] = 0.f; ssq[k] = 0.f;
    }
    if (blockIdx.x == 0) {
        for (int k = tid; k < 2 * HID; k += 256) { g_s1[k] = 0.f; g_s2[k] = 0.f; }
    }
    __syncthreads();
    const int warp = tid >> 5, lane = tid & 31;
    const float* dwt = g_dwT + (size_t)t * N * DIM;
    float* xsO = out_xs + (size_t)t * N * DIM;
    for (int it = 0; it < 4; ++it) {
        const int i = blockIdx.x * 32 + it * 8 + warp;
        float sz = 0.f, zdw = 0.f, xx = 0.f;
        float zv[4], dwv[4], xv[4];
#pragma unroll
        for (int c2 = 0; c2 < 4; ++c2) {
            int j = lane + 32 * c2;
            if (j < DIM) {
                float h = g_h3[(size_t)i * DIM + j];
                zv[c2]  = fmaf(h, sAz[j], sBz[j]);
                dwv[c2] = dwt[(size_t)i * DIM + j];
                xv[c2]  = g_x[(size_t)i * DIM + j];
                sz  += zv[c2];
                zdw += zv[c2] * dwv[c2];
                xx  += xv[c2] * xv[c2];
            }
        }
#pragma unroll
        for (int o = 16; o; o >>= 1) {
            sz  += __shfl_xor_sync(~0u, sz, o);
            zdw += __shfl_xor_sync(~0u, zdw, o);
            xx  += __shfl_xor_sync(~0u, xx, o);
        }
        const float u = fminf(fmaxf(-sz, -1.f), 1.f);
        if (lane == 0) {
            float y = g_y[i];
            y = y - DT * 0.5f * (xx + u * u) + DT * sz * u + zdw;
            g_y[i] = y;
            out_us[(size_t)t * N + i] = u;
        }
#pragma unroll
        for (int c2 = 0; c2 < 4; ++c2) {
            int j = lane + 32 * c2;
            if (j < DIM) {
                float xo = xv[c2];
                xsO[(size_t)i * DIM + j] = xo;
                float xn = fmaf(xo, 1.0f - DT, fmaf(u, DT, dwv[c2]));
                g_x[(size_t)i * DIM + j] = xn;
                atomicAdd(&ssum[j], xn);
                atomicAdd(&ssq[j], xn * xn);
            }
        }
    }
    __syncthreads();
    for (int k = tid; k < DIM; k += 256) {
        atomicAdd(&g_s0[k], ssum[k]);
        atomicAdd(&g_s0[DIM + k], ssq[k]);
    }
}

// ---------------------------------------------------------------------------
// Fused GEMM + BN:  out[N,C] = bnaffine(in)[N,K] (opt relu) @ W[C,K]^T (+bias)
// Epilogue accumulates next-layer BN stats. 32 rows x 128(pad) cols per block.
// 256 threads = 16 rowgroups (2 rows) x 16 colgroups (8 cols).
// ---------------------------------------------------------------------------
template <int LAYER>
__global__ void __launch_bounds__(256) gemm_bn(const float* __restrict__ W,
                                               const float* __restrict__ bnw,
                                               const float* __restrict__ bnb,
                                               const float* __restrict__ bias) {
    constexpr int  K    = (LAYER == 1) ? DIM : HID;
    constexpr int  C    = (LAYER == 3) ? DIM : HID;
    constexpr bool RELU = (LAYER != 1);
    constexpr bool BIAS = (LAYER == 3);
    constexpr int  CP   = 132;   // padded col stride (16B-aligned, conflict-safe)

    const float* in   = (LAYER == 1) ? (const float*)g_x
                      : (LAYER == 2) ? (const float*)g_h1 : (const float*)g_h2;
    const float* stIn = (LAYER == 1) ? (const float*)g_s0
                      : (LAYER == 2) ? (const float*)g_s1 : (const float*)g_s2;
    float* out  = (LAYER == 1) ? g_h1 : (LAYER == 2) ? g_h2 : g_h3;
    float* stOut = (LAYER == 1) ? g_s1 : (LAYER == 2) ? g_s2 : g_s3;

    extern __shared__ float sm[];
    float* sW = sm;                 // K*CP
    float* sX = sW + K * CP;        // K*34  (transposed input tile)
    float* sA = sX + K * 34;        // K
    float* sB = sA + K;             // K

    const int tid  = threadIdx.x;
    const int rowg = tid & 15, colg = tid >> 4;
    const int row0 = blockIdx.x * 32;

    // rotate-zero the stats buffer that is safe to clear in this phase
    if (blockIdx.x == 0) {
        if (LAYER == 1) for (int k = tid; k < 2 * DIM; k += 256) g_s3[k] = 0.f;
        if (LAYER == 2) for (int k = tid; k < 2 * DIM; k += 256) g_s0[k] = 0.f;
    }

    // BN affine of the input layer
    for (int k = tid; k < K; k += 256) {
        float a, c;
        affine_coef(stIn[k], stIn[K + k], bnw[k], bnb[k], a, c);
        sA[k] = a; sB[k] = c;
    }
    // zero pad columns of sW so pad accumulators stay 0
    for (int idx = tid; idx < K * (CP - C); idx += 256) {
        int k = idx / (CP - C), c = idx - k * (CP - C);
        sW[k * CP + C + c] = 0.f;
    }
    __syncthreads();

    // W is [C,K] row-major -> sW[k][c]
    for (int idx = tid; idx < C * K; idx += 256) {
        int c = idx / K, k = idx - c * K;
        sW[k * CP + c] = W[idx];
    }
    // input tile (affine + optional relu), transposed to sX[k][r]
    for (int idx = tid; idx < 32 * K; idx += 256) {
        int r = idx / K, k = idx - r * K;
        float v = in[(size_t)(row0 + r) * K + k];
        v = fmaf(v, sA[k], sB[k]);
        if (RELU) v = fmaxf(v, 0.f);
        sX[k * 34 + r] = v;
    }
    __syncthreads();

    float acc0[8], acc1[8];
#pragma unroll
    for (int c = 0; c < 8; ++c) { acc0[c] = 0.f; acc1[c] = 0.f; }
    const int cb = colg * 8;

#pragma unroll 2
    for (int k = 0; k < K; ++k) {
        float2 xv = *reinterpret_cast<const float2*>(&sX[k * 34 + 2 * rowg]);
        float4 w0 = *reinterpret_cast<const float4*>(&sW[k * CP + cb]);
        float4 w1 = *reinterpret_cast<const float4*>(&sW[k * CP + cb + 4]);
        float wv[8] = {w0.x, w0.y, w0.z, w0.w, w1.x, w1.y, w1.z, w1.w};
#pragma unroll
        for (int c = 0; c < 8; ++c) {
            acc0[c] = fmaf(xv.x, wv[c], acc0[c]);
            acc1[c] = fmaf(xv.y, wv[c], acc1[c]);
        }
    }

    // epilogue: bias, store, per-column stats (shfl-reduce over 16 rowgroups)
    const int r0 = row0 + 2 * rowg;
    float vs[8], vq[8];
#pragma unroll
    for (int c = 0; c < 8; ++c) {
        const int col = cb + c;
        float v0 = acc0[c], v1 = acc1[c];
        if (BIAS && col < C) { float b = __ldg(&bias[col]); v0 += b; v1 += b; }
        if (col < C) {
            out[(size_t)r0 * C + col]       = v0;
            out[(size_t)(r0 + 1) * C + col] = v1;
        }
        vs[c] = v0 + v1;
        vq[c] = v0 * v0 + v1 * v1;
    }
#pragma unroll
    for (int c = 0; c < 8; ++c) {
        float s = vs[c], q = vq[c];
#pragma unroll
        for (int o = 8; o; o >>= 1) {
            s += __shfl_xor_sync(~0u, s, o);
            q += __shfl_xor_sync(~0u, q, o);
        }
        if ((tid & 15) == 0) {
            const int col = cb + c;
            if (col < C) {
                atomicAdd(&stOut[col], s);
                atomicAdd(&stOut[C + col], q);
            }
        }
    }
}

// ---------------------------------------------------------------------------
// Final step (t = 49): u/y update only, ye, loss partials, outputs
// ---------------------------------------------------------------------------
__global__ void __launch_bounds__(256) finalK(const float* __restrict__ bn3w,
                                              const float* __restrict__ bn3b,
                                              float* __restrict__ out_y,
                                              float* __restrict__ out_ye,
                                              float* __restrict__ out_xs,
                                              float* __restrict__ out_us) {
    __shared__ float sAz[DIM], sBz[DIM];
    const int tid = threadIdx.x;
    for (int k = tid; k < DIM; k += 256) {
        float a, c;
        affine_coef(g_s3[k], g_s3[DIM + k], bn3w[k], bn3b[k], a, c);
        sAz[k] = a * 1e-4f;
        sBz[k] = c * 1e-4f;
    }
    __syncthreads();
    const int warp = tid >> 5, lane = tid & 31;
    const float* dwt = g_dwT + (size_t)(T - 1) * N * DIM;
    float* xsO = out_xs + (size_t)(T - 1) * N * DIM;
    for (int it = 0; it < 4; ++it) {
        const int i = blockIdx.x * 32 + it * 8 + warp;
        float sz = 0.f, zdw = 0.f, xx = 0.f;
#pragma unroll
        for (int c2 = 0; c2 < 4; ++c2) {
            int j = lane + 32 * c2;
            if (j < DIM) {
                float h  = g_h3[(size_t)i * DIM + j];
                float z  = fmaf(h, sAz[j], sBz[j]);
                float dw = dwt[(size_t)i * DIM + j];
                float x  = g_x[(size_t)i * DIM + j];
                xsO[(size_t)i * DIM + j] = x;
                sz += z; zdw += z * dw; xx += x * x;
            }
        }
#pragma unroll
        for (int o = 16; o; o >>= 1) {
            sz  += __shfl_xor_sync(~0u, sz, o);
            zdw += __shfl_xor_sync(~0u, zdw, o);
            xx  += __shfl_xor_sync(~0u, xx, o);
        }
        const float u = fminf(fmaxf(-sz, -1.f), 1.f);
        if (lane == 0) {
            float y = g_y[i];
            y = y - DT * 0.5f * (xx + u * u) + DT * sz * u + zdw;
            out_y[i]  = y;
            float ye  = 0.5f * xx;
            out_ye[i] = ye;
            out_us[(size_t)(T - 1) * N + i] = u;
            float d = y - ye, ad = fabsf(d);
            float sl1 = (ad < 1.f) ? 0.5f * d * d : ad - 0.5f;
            atomicAdd(&g_acc[0], sl1);
            atomicAdd(&g_acc[1], ye);
        }
    }
}

__global__ void lossK(float* __restrict__ out) {
    float m1 = g_acc[0] * (1.0f / N);
    float m2 = g_acc[1] * (1.0f / N);
    out[0] = 100.0f * (m1 + m2 * m2);   // 2 * DELTA_CLIP * (sl1 + mean(ye)^2)
}

// ---------------------------------------------------------------------------
// Launcher (graph-capturable: kernel launches only)
// ---------------------------------------------------------------------------
extern "C" void kernel_launch(void* const* d_in, const int* in_sizes, int n_in,
                              void* d_out, int out_size) {
    const float* dw    = (const float*)d_in[0];
    const float* yinit = (const float*)d_in[1];
    const float* zinit = (const float*)d_in[2];
    const float* bn0w  = (const float*)d_in[3];
    const float* bn0b  = (const float*)d_in[4];
    const float* w1    = (const float*)d_in[5];
    const float* bn1w  = (const float*)d_in[6];
    const float* bn1b  = (const float*)d_in[7];
    const float* w2    = (const float*)d_in[8];
    const float* bn2w  = (const float*)d_in[9];
    const float* bn2b  = (const float*)d_in[10];
    const float* w3    = (const float*)d_in[11];
    const float* b3    = (const float*)d_in[12];
    const float* bn3w  = (const float*)d_in[13];
    const float* bn3b  = (const float*)d_in[14];

    float* out    = (float*)d_out;
    float* out_y  = out + 1;
    float* out_ye = out + 1 + N;
    float* out_xs = out + 1 + 2 * N;
    float* out_us = out_xs + (size_t)T * N * DIM;

    const size_t sm1 = (size_t)(DIM * 132 + DIM * 34 + 2 * DIM) * sizeof(float);
    const size_t sm2 = (size_t)(HID * 132 + HID * 34 + 2 * HID) * sizeof(float);
    cudaFuncSetAttribute(gemm_bn<1>, cudaFuncAttributeMaxDynamicSharedMemorySize, (int)sm1);
    cudaFuncSetAttribute(gemm_bn<2>, cudaFuncAttributeMaxDynamicSharedMemorySize, (int)sm2);
    cudaFuncSetAttribute(gemm_bn<3>, cudaFuncAttributeMaxDynamicSharedMemorySize, (int)sm2);

    initK<<<1, 256>>>();
    transpose_dw<<<dim3(N * DIM / 32, 2), dim3(32, 8)>>>(dw);

    // step 0
    phaseA0<<<128, 256>>>(zinit, yinit, out_xs, out_us);
    gemm_bn<1><<<128, 256, sm1>>>(w1, bn0w, bn0b, nullptr);
    gemm_bn<2><<<128, 256, sm2>>>(w2, bn1w, bn1b, nullptr);
    gemm_bn<3><<<128, 256, sm2>>>(w3, bn2w, bn2b, b3);

    // steps 1..48
    for (int t = 1; t < T - 1; ++t) {
        phaseA<<<128, 256>>>(t, bn3w, bn3b, out_xs, out_us);
        gemm_bn<1><<<128, 256, sm1>>>(w1, bn0w, bn0b, nullptr);
        gemm_bn<2><<<128, 256, sm2>>>(w2, bn1w, bn1b, nullptr);
        gemm_bn<3><<<128, 256, sm2>>>(w3, bn2w, bn2b, b3);
    }

    // final step t = 49 (u/y only) + loss
    finalK<<<128, 256>>>(bn3w, bn3b, out_y, out_ye, out_xs, out_us);
    lossK<<<1, 1>>>(out);
}

// round 6
// speedup vs baseline: 2.4716x; 2.4643x over previous
#include <cuda_runtime.h>

// ---------------------------------------------------------------------------
// Problem constants + smem layout
// ---------------------------------------------------------------------------
namespace {
constexpr int   N    = 4096;
constexpr int   DIM  = 100;
constexpr int   HID  = 110;
constexpr int   T    = 50;
constexpr float DT   = 0.02f;
constexpr float EPS  = 1e-6f;
constexpr int   GRID = 128;       // co-resident blocks (1 per SM)
constexpr int   NT   = 512;       // threads per block
constexpr int   WS   = 112;       // weight tile col stride (16B aligned quads)

// smem offsets in floats
constexpr int OF_W1 = 0;                    // [100][112]
constexpr int OF_W2 = OF_W1 + DIM * WS;     // [110][112]
constexpr int OF_W3 = OF_W2 + HID * WS;     // [110][112]
constexpr int OF_X  = OF_W3 + HID * WS;     // [100][34]  x state  [k][r]
constexpr int OF_A  = OF_X + DIM * 34;      // [110][34]  h1 / h3 tile
constexpr int OF_B  = OF_A + HID * 34;      // [110][34]  h2 tile
constexpr int OF_D  = OF_B + HID * 34;      // [110][64]  duplicated gemm input
constexpr int OF_Y  = OF_D + HID * 64;      // [32]       y state
constexpr int OF_AF = OF_Y + 32;            // [112] affine a
constexpr int OF_BF = OF_AF + 112;          // [112] affine c
constexpr int SMF   = OF_BF + 112;          // 54016 floats = 216064 bytes
}

// ---------------------------------------------------------------------------
// Global state
// ---------------------------------------------------------------------------
__device__ float g_dwT[(size_t)T * N * DIM];   // dw transposed [T][N][DIM]
__device__ float g_s0[2 * DIM];
__device__ float g_s1[2 * HID];
__device__ float g_s2[2 * HID];
__device__ float g_s3[2 * DIM];
__device__ float g_acc[2];
__device__ unsigned g_cnt;
__device__ volatile unsigned g_gen;

__device__ __forceinline__ void affine_coef(float sum, float sumsq, float w,
                                            float b, float& a, float& c) {
    float mean = sum * (1.0f / N);
    float var  = fmaf(-mean, mean, sumsq * (1.0f / N)) + EPS;
    float r    = rsqrtf(var);
    r = r * (1.5f - 0.5f * var * r * r);   // Newton refine
    a = w * r;
    c = fmaf(-mean, a, b);
}

// grid-wide barrier: all GRID blocks are resident by construction
__device__ __forceinline__ void gbar(unsigned& target) {
    __syncthreads();
    if (threadIdx.x == 0) {
        __threadfence();
        if (atomicAdd(&g_cnt, 1u) == (unsigned)(GRID - 1)) {
            atomicExch(&g_cnt, 0u);
            __threadfence();
            g_gen = target;
        } else {
            while (g_gen < target) { __nanosleep(32); }
        }
        __threadfence();
    }
    __syncthreads();
    ++target;
}

#define FMA2(acc, a, b) \
    asm("fma.rn.f32x2 %0, %1, %2, %0;" : "+l"(acc) : "l"(a), "l"(b))

// ---------------------------------------------------------------------------
__global__ void initK() {
    int tid = threadIdx.x;
    for (int k = tid; k < 2 * DIM; k += 256) { g_s0[k] = 0.f; g_s3[k] = 0.f; }
    for (int k = tid; k < 2 * HID; k += 256) { g_s1[k] = 0.f; g_s2[k] = 0.f; }
    if (tid == 0) { g_acc[0] = 0.f; g_acc[1] = 0.f; g_cnt = 0u; g_gen = 0u; }
}

// Transpose dw [N*DIM, T] -> [T, N*DIM]
__global__ void transpose_dw(const float* __restrict__ in) {
    __shared__ float s[32][33];
    const int ij0 = blockIdx.x * 32;
    const int t0  = blockIdx.y * 32;
    const int tx  = threadIdx.x, ty = threadIdx.y;
#pragma unroll
    for (int i = 0; i < 32; i += 8) {
        int t = t0 + tx;
        int ij = ij0 + ty + i;
        if (t < T) s[ty + i][tx] = in[(size_t)ij * T + t];
    }
    __syncthreads();
#pragma unroll
    for (int i = 0; i < 32; i += 8) {
        int t = t0 + ty + i;
        int ij = ij0 + tx;
        if (t < T) g_dwT[(size_t)t * (N * DIM) + ij] = s[tx][ty + i];
    }
}

// ---------------------------------------------------------------------------
// BN affine (+relu) on [K x 32] tile -> duplicated layout dup[k*64 + 2r] = {v,v}
// Contains __syncthreads: all threads must call.
// ---------------------------------------------------------------------------
template <int K, bool RELU>
__device__ __forceinline__ void prep(const float* __restrict__ gStat,
                                     const float* __restrict__ bnw,
                                     const float* __restrict__ bnb,
                                     const float* __restrict__ src,
                                     float* __restrict__ dup,
                                     float* __restrict__ sAf,
                                     float* __restrict__ sBf) {
    const int tid = threadIdx.x;
    for (int k = tid; k < K; k += NT) {
        float a, c;
        affine_coef(__ldcg(&gStat[k]), __ldcg(&gStat[K + k]), bnw[k], bnb[k], a, c);
        sAf[k] = a; sBf[k] = c;
    }
    __syncthreads();
    for (int idx = tid; idx < K * 32; idx += NT) {
        int k = idx >> 5, r = idx & 31;
        float v = fmaf(src[k * 34 + r], sAf[k], sBf[k]);
        if (RELU) v = fmaxf(v, 0.f);
        *reinterpret_cast<float2*>(dup + (k << 6) + 2 * r) = make_float2(v, v);
    }
    __syncthreads();
}

// ---------------------------------------------------------------------------
// GEMM: sO[c*34+r] = sum_k dup[k][r] * sW[k*WS+c]  (+ bias[c]); FFMA2 mainloop
// warp-pair covers 16 cols x 32 rows; lane: 2 rows x 4 cols. No syncs inside.
// ---------------------------------------------------------------------------
template <int K, int C, bool BIAS>
__device__ __forceinline__ void gemm(const float* __restrict__ sD,
                                     const float* __restrict__ sW,
                                     float* __restrict__ sO,
                                     const float* __restrict__ bias) {
    const int warp = threadIdx.x >> 5, lane = threadIdx.x & 31;
    const int cb = (warp >> 1) * 16;
    if (cb >= C) return;
    const int r0 = ((warp & 1) << 4) + ((lane & 7) << 1);
    const int c0 = cb + ((lane >> 3) << 2);
    unsigned long long a00 = 0ull, a01 = 0ull, a10 = 0ull, a11 = 0ull;
#pragma unroll 2
    for (int k = 0; k < K; ++k) {
        const float* dk = sD + (k << 6) + 2 * r0;
        unsigned long long x0 = *reinterpret_cast<const unsigned long long*>(dk);
        unsigned long long x1 = *reinterpret_cast<const unsigned long long*>(dk + 2);
        ulonglong2 w = *reinterpret_cast<const ulonglong2*>(sW + k * WS + c0);
        FMA2(a00, w.x, x0);
        FMA2(a01, w.y, x0);
        FMA2(a10, w.x, x1);
        FMA2(a11, w.y, x1);
    }
    float v00, v01, v02, v03, v10, v11, v12, v13;
    asm("mov.b64 {%0,%1}, %2;" : "=f"(v00), "=f"(v01) : "l"(a00));
    asm("mov.b64 {%0,%1}, %2;" : "=f"(v02), "=f"(v03) : "l"(a01));
    asm("mov.b64 {%0,%1}, %2;" : "=f"(v10), "=f"(v11) : "l"(a10));
    asm("mov.b64 {%0,%1}, %2;" : "=f"(v12), "=f"(v13) : "l"(a11));
    float c0v[4] = {v00, v01, v02, v03};
    float c1v[4] = {v10, v11, v12, v13};
#pragma unroll
    for (int c = 0; c < 4; ++c) {
        const int col = c0 + c;
        if (col < C) {
            float b = BIAS ? __ldg(&bias[col]) : 0.f;
            *reinterpret_cast<float2*>(&sO[col * 34 + r0]) =
                make_float2(c0v[c] + b, c1v[c] + b);
        }
    }
}

// per-column sum / sumsq over [C x 32] tile -> global RED
template <int C>
__device__ __forceinline__ void statp(const float* __restrict__ sO,
                                      float* __restrict__ gStat) {
    const int tid = threadIdx.x;
    if (tid < C) {
        float s = 0.f, q = 0.f;
#pragma unroll
        for (int r = 0; r < 32; r += 2) {
            float2 v = *reinterpret_cast<const float2*>(&sO[tid * 34 + r]);
            s += v.x + v.y;
            q = fmaf(v.x, v.x, fmaf(v.y, v.y, q));
        }
        atomicAdd(&gStat[tid], s);
        atomicAdd(&gStat[C + tid], q);
    }
}

// ---------------------------------------------------------------------------
// The persistent kernel: all 50 steps in one launch
// ---------------------------------------------------------------------------
__global__ void __launch_bounds__(NT, 1) persistK(
    const float* __restrict__ zinit, const float* __restrict__ yinit,
    const float* __restrict__ bn0w, const float* __restrict__ bn0b,
    const float* __restrict__ w1,   const float* __restrict__ bn1w,
    const float* __restrict__ bn1b, const float* __restrict__ w2,
    const float* __restrict__ bn2w, const float* __restrict__ bn2b,
    const float* __restrict__ w3,   const float* __restrict__ b3,
    const float* __restrict__ bn3w, const float* __restrict__ bn3b,
    float* __restrict__ out_loss, float* __restrict__ out_y,
    float* __restrict__ out_ye,   float* __restrict__ out_xs,
    float* __restrict__ out_us)
{
    extern __shared__ float sm[];
    float* sW1 = sm + OF_W1;
    float* sW2 = sm + OF_W2;
    float* sW3 = sm + OF_W3;
    float* sX  = sm + OF_X;
    float* sTa = sm + OF_A;
    float* sTb = sm + OF_B;
    float* sD  = sm + OF_D;
    float* sy  = sm + OF_Y;
    float* sAf = sm + OF_AF;
    float* sBf = sm + OF_BF;

    const int tid   = threadIdx.x;
    const int warp  = tid >> 5, lane = tid & 31;
    const int rbase = blockIdx.x * 32;
    unsigned target = 1;

    // zero weight region (pads) + x state
    for (int i = tid; i < OF_X; i += NT) sm[i] = 0.f;
    for (int i = tid; i < DIM * 34; i += NT) sX[i] = 0.f;
    __syncthreads();
    // load weights once: sW[k*WS + c] = W[c*K + k]
    for (int idx = tid; idx < HID * DIM; idx += NT) {   // W1 [110,100]
        int c = idx / DIM, k = idx - c * DIM;
        sW1[k * WS + c] = w1[idx];
    }
    for (int idx = tid; idx < HID * HID; idx += NT) {   // W2 [110,110]
        int c = idx / HID, k = idx - c * HID;
        sW2[k * WS + c] = w2[idx];
    }
    for (int idx = tid; idx < DIM * HID; idx += NT) {   // W3 [100,110]
        int c = idx / HID, k = idx - c * HID;
        sW3[k * WS + c] = w3[idx];
    }
    const float y0 = yinit[0];

    for (int t = 0; t < T; ++t) {
        const bool first = (t == 0), last = (t == T - 1);

        // ---------------- phase A ----------------
        if (!first) {
            for (int k = tid; k < DIM; k += NT) {
                float a, c;
                affine_coef(__ldcg(&g_s3[k]), __ldcg(&g_s3[DIM + k]),
                            bn3w[k], bn3b[k], a, c);
                sAf[k] = a * 1e-4f;   // /DIM (subnet) * /DIM (z update)
                sBf[k] = c * 1e-4f;
            }
        }
        if (!last && blockIdx.x == 0)
            for (int k = tid; k < 2 * HID; k += NT) __stcg(&g_s2[k], 0.f);
        __syncthreads();

        const float* dwt = g_dwT + ((size_t)t * N + rbase) * DIM;
        float* xsO = out_xs + ((size_t)t * N + rbase) * DIM;

#pragma unroll
        for (int it = 0; it < 2; ++it) {
            const int r = it * 16 + warp;
            const int i = rbase + r;
            float sz = 0.f, zdw = 0.f, xx = 0.f;
            float xo[4], dwv[4];
#pragma unroll
            for (int c2 = 0; c2 < 4; ++c2) {
                int j = lane + 32 * c2;
                xo[c2] = 0.f; dwv[c2] = 0.f;
                if (j < DIM) {
                    float z = first ? zinit[j]
                                    : fmaf(sTa[j * 34 + r], sAf[j], sBf[j]);
                    dwv[c2] = dwt[(size_t)r * DIM + j];
                    xo[c2]  = sX[j * 34 + r];
                    sz  += z;
                    zdw += z * dwv[c2];
                    xx  += xo[c2] * xo[c2];
                }
            }
#pragma unroll
            for (int o = 16; o; o >>= 1) {
                sz  += __shfl_xor_sync(~0u, sz, o);
                zdw += __shfl_xor_sync(~0u, zdw, o);
                xx  += __shfl_xor_sync(~0u, xx, o);
            }
            const float u = fminf(fmaxf(-sz, -1.f), 1.f);
            float yv = first ? y0 : sy[r];
            yv = yv - DT * 0.5f * (xx + u * u) + DT * sz * u + zdw;
            if (lane == 0) {
                out_us[(size_t)t * N + i] = u;
                if (last) {
                    out_y[i] = yv;
                    float ye = 0.5f * xx;
                    out_ye[i] = ye;
                    float d = yv - ye, ad = fabsf(d);
                    atomicAdd(&g_acc[0], (ad < 1.f) ? 0.5f * d * d : ad - 0.5f);
                    atomicAdd(&g_acc[1], ye);
                } else {
                    sy[r] = yv;
                }
            }
#pragma unroll
            for (int c2 = 0; c2 < 4; ++c2) {
                int j = lane + 32 * c2;
                if (j < DIM) {
                    xsO[(size_t)r * DIM + j] = xo[c2];
                    if (!last)
                        sX[j * 34 + r] = fmaf(xo[c2], 1.f - DT,
                                              fmaf(u, DT, dwv[c2]));
                }
            }
        }
        __syncthreads();

        if (last) {
            gbar(target);
            if (blockIdx.x == 0 && tid == 0) {
                float m1 = __ldcg(&g_acc[0]) * (1.0f / N);
                float m2 = __ldcg(&g_acc[1]) * (1.0f / N);
                out_loss[0] = 100.0f * (m1 + m2 * m2);
            }
            break;
        }

        statp<DIM>(sX, g_s0);
        gbar(target);

        // ---------------- GEMM1: h1 = bn0(x) @ W1^T ----------------
        if (blockIdx.x == 0)
            for (int k = tid; k < 2 * DIM; k += NT) __stcg(&g_s3[k], 0.f);
        prep<DIM, false>(g_s0, bn0w, bn0b, sX, sD, sAf, sBf);
        gemm<DIM, HID, false>(sD, sW1, sTa, nullptr);
        __syncthreads();
        statp<HID>(sTa, g_s1);
        gbar(target);

        // ---------------- GEMM2: h2 = relu(bn1(h1)) @ W2^T ----------------
        if (blockIdx.x == 0)
            for (int k = tid; k < 2 * DIM; k += NT) __stcg(&g_s0[k], 0.f);
        prep<HID, true>(g_s1, bn1w, bn1b, sTa, sD, sAf, sBf);
        gemm<HID, HID, false>(sD, sW2, sTb, nullptr);
        __syncthreads();
        statp<HID>(sTb, g_s2);
        gbar(target);

        // ---------------- GEMM3: h3 = relu(bn2(h2)) @ W3^T + b3 ----------------
        if (blockIdx.x == 0)
            for (int k = tid; k < 2 * HID; k += NT) __stcg(&g_s1[k], 0.f);
        prep<HID, true>(g_s2, bn2w, bn2b, sTb, sD, sAf, sBf);
        gemm<HID, DIM, true>(sD, sW3, sTa, b3);
        __syncthreads();
        statp<DIM>(sTa, g_s3);
        gbar(target);
    }
}

// ---------------------------------------------------------------------------
// Launcher
// ---------------------------------------------------------------------------
extern "C" void kernel_launch(void* const* d_in, const int* in_sizes, int n_in,
                              void* d_out, int out_size) {
    const float* dw    = (const float*)d_in[0];
    const float* yinit = (const float*)d_in[1];
    const float* zinit = (const float*)d_in[2];
    const float* bn0w  = (const float*)d_in[3];
    const float* bn0b  = (const float*)d_in[4];
    const float* w1    = (const float*)d_in[5];
    const float* bn1w  = (const float*)d_in[6];
    const float* bn1b  = (const float*)d_in[7];
    const float* w2    = (const float*)d_in[8];
    const float* bn2w  = (const float*)d_in[9];
    const float* bn2b  = (const float*)d_in[10];
    const float* w3    = (const float*)d_in[11];
    const float* b3    = (const float*)d_in[12];
    const float* bn3w  = (const float*)d_in[13];
    const float* bn3b  = (const float*)d_in[14];

    float* out    = (float*)d_out;
    float* out_y  = out + 1;
    float* out_ye = out + 1 + N;
    float* out_xs = out + 1 + 2 * N;
    float* out_us = out_xs + (size_t)T * N * DIM;

    static int attr_done = 0;
    if (!attr_done) {
        cudaFuncSetAttribute(persistK,
                             cudaFuncAttributeMaxDynamicSharedMemorySize,
                             SMF * (int)sizeof(float));
        attr_done = 1;
    }

    initK<<<1, 256>>>();
    transpose_dw<<<dim3(N * DIM / 32, 2), dim3(32, 8)>>>(dw);
    persistK<<<GRID, NT, SMF * sizeof(float)>>>(
        zinit, yinit, bn0w, bn0b, w1, bn1w, bn1b, w2, bn2w, bn2b,
        w3, b3, bn3w, bn3b, out, out_y, out_ye, out_xs, out_us);
}